// round 1
// baseline (speedup 1.0000x reference)
#include <cuda_runtime.h>

#define NS 25
#define NC 80
#define CD (NC*NC)          // 6400
#define BATCH 64
#define TIME 400
#define BT (BATCH*TIME)     // 25600
#define M_ELEMS (BT*NC)     // 2,048,000

#define R 32                // bt rows per C-block
#define CTHREADS 320        // 320 threads * 4 floats = 1280 cols; 5 chunks cover 6400

// Packed dual-FMA: d.lo = a.lo*b.lo + d.lo ; d.hi = a.hi*b.hi + d.hi
__device__ __forceinline__ void ffma2(unsigned long long &acc,
                                      unsigned long long a,
                                      unsigned long long b) {
    asm("fma.rn.f32x2 %0, %1, %2, %0;" : "+l"(acc) : "l"(a), "l"(b));
}

__device__ __forceinline__ float softplus_f(float x) { return log1pf(expf(x)); }

// ---------------------------------------------------------------------------
// C_t kernel: block computes a [R x 1280] tile of C = A @ D_flat.
// j-outer loop: 1 LDG.128 of D + R broadcast LDS.64 of packed a + 2R FFMA2.
// ---------------------------------------------------------------------------
__global__ __launch_bounds__(CTHREADS, 1)
void c_kernel(const float* __restrict__ alpha,
              const float* __restrict__ D,
              const float* __restrict__ asc,
              float* __restrict__ C)
{
    __shared__ unsigned long long a2[R * NS];   // {a,a} pairs, 6.4 KB
    __shared__ float scale_s[NS];

    const int tid = threadIdx.x;
    if (tid < NS) scale_s[tid] = softplus_f(asc[tid]);
    __syncthreads();

    const int bt0 = blockIdx.y * R;
    for (int i = tid; i < R * NS; i += CTHREADS) {
        const int r = i / NS, j = i % NS;
        const float v = alpha[(bt0 + r) * NS + j] * scale_s[j];
        float2 p = make_float2(v, v);
        a2[i] = *reinterpret_cast<unsigned long long*>(&p);
    }
    __syncthreads();

    const int col4 = blockIdx.x * CTHREADS + tid;          // float4 column, 0..1599
    const char* Dbase = reinterpret_cast<const char*>(D) + (size_t)col4 * 16;

    unsigned long long acc[R][2];
    #pragma unroll
    for (int r = 0; r < R; r++) { acc[r][0] = 0ull; acc[r][1] = 0ull; }

    #pragma unroll 5
    for (int j = 0; j < NS; j++) {
        const ulonglong2 d =
            *reinterpret_cast<const ulonglong2*>(Dbase + (size_t)j * (CD * 4));
        #pragma unroll
        for (int r = 0; r < R; r++) {
            const unsigned long long aa = a2[r * NS + j];  // broadcast LDS.64
            ffma2(acc[r][0], d.x, aa);
            ffma2(acc[r][1], d.y, aa);
        }
    }

    float* Cbase = C + (size_t)bt0 * CD + (size_t)col4 * 4;
    #pragma unroll
    for (int r = 0; r < R; r++) {
        ulonglong2 u;
        u.x = acc[r][0];
        u.y = acc[r][1];
        __stcs(reinterpret_cast<float4*>(Cbase + (size_t)r * CD),
               *reinterpret_cast<float4*>(&u));
    }
}

// ---------------------------------------------------------------------------
// m_t kernel: block handles 16 bt rows x 80 channels. mu cached in smem.
// ---------------------------------------------------------------------------
__global__ __launch_bounds__(256)
void m_kernel(const float* __restrict__ alpha,
              const float* __restrict__ mu,
              const float* __restrict__ asc,
              float* __restrict__ m)
{
    __shared__ float mu_s[NS * NC];    // 8 KB
    __shared__ float a_s[16 * NS];
    __shared__ float scale_s[NS];

    const int tid = threadIdx.x;
    if (tid < NS) scale_s[tid] = softplus_f(asc[tid]);
    __syncthreads();

    for (int i = tid; i < NS * NC; i += 256) mu_s[i] = mu[i];

    const int bt0 = blockIdx.x * 16;
    for (int i = tid; i < 16 * NS; i += 256) {
        const int r = i / NS, j = i % NS;
        a_s[i] = alpha[(bt0 + r) * NS + j] * scale_s[j];
    }
    __syncthreads();

    for (int o = tid; o < 16 * NC; o += 256) {
        const int r = o / NC, c = o % NC;
        float s = 0.0f;
        #pragma unroll
        for (int j = 0; j < NS; j++) s = fmaf(a_s[r * NS + j], mu_s[j * NC + c], s);
        m[(size_t)(bt0 + r) * NC + c] = s;
    }
}

extern "C" void kernel_launch(void* const* d_in, const int* in_sizes, int n_in,
                              void* d_out, int out_size)
{
    const float* alpha = (const float*)d_in[0];   // [64,400,25]
    const float* mu    = (const float*)d_in[1];   // [25,80]
    const float* D     = (const float*)d_in[2];   // [25,80,80]
    const float* asc   = (const float*)d_in[3];   // [25]

    float* out = (float*)d_out;
    float* m_out = out;                 // [64,400,80]
    float* c_out = out + M_ELEMS;       // [64,400,80,80]

    m_kernel<<<BT / 16, 256>>>(alpha, mu, asc, m_out);
    c_kernel<<<dim3(5, BT / R), CTHREADS>>>(alpha, D, asc, c_out);
}

// round 2
// speedup vs baseline: 1.0497x; 1.0497x over previous
#include <cuda_runtime.h>

#define NS 25
#define NC 80
#define CD (NC*NC)          // 6400
#define BATCH 64
#define TIME 400
#define BT (BATCH*TIME)     // 25600
#define M_ELEMS (BT*NC)     // 2,048,000

#define R 32                // bt rows per block
#define CTHREADS 320        // 320 threads * 4 floats = 1280 cols; 5 chunks cover 6400

// Packed dual-FMA via f32x2 (only reachable from PTX; doubles FFMA throughput)
__device__ __forceinline__ void ffma2(unsigned long long &acc,
                                      unsigned long long a,
                                      unsigned long long b) {
    asm("fma.rn.f32x2 %0, %1, %2, %0;" : "+l"(acc) : "l"(a), "l"(b));
}

__device__ __forceinline__ float softplus_f(float x) { return log1pf(expf(x)); }

// ---------------------------------------------------------------------------
// Fused kernel.
//  blockIdx.x in [0,5): C tile  [R x 1280] of C = A @ D_flat
//  blockIdx.x == 5    : m tile  [R x 80]   of m = A @ mu     (light block)
// a-pair table layout [j][r] so LDS.128 serves two rows per load.
// ---------------------------------------------------------------------------
__global__ __launch_bounds__(CTHREADS, 1)
void fused_kernel(const float* __restrict__ alpha,
                  const float* __restrict__ mu,
                  const float* __restrict__ D,
                  const float* __restrict__ asc,
                  float* __restrict__ m_out,
                  float* __restrict__ C)
{
    __shared__ float scale_s[NS];
    __shared__ __align__(16) unsigned long long a2s[NS * R];  // [j][r] pairs, 6.4 KB
    __shared__ float mu_s[NS * NC];                           // 8 KB (m path only)

    const int tid = threadIdx.x;
    if (tid < NS) scale_s[tid] = softplus_f(asc[tid]);
    __syncthreads();

    const int bt0 = blockIdx.y * R;

    // All blocks build the scaled-alpha pair table in [j][r] layout.
    for (int i = tid; i < R * NS; i += CTHREADS) {
        const int r = i & (R - 1);
        const int j = i >> 5;
        const float v = alpha[(bt0 + r) * NS + j] * scale_s[j];
        float2 p = make_float2(v, v);
        a2s[j * R + r] = *reinterpret_cast<unsigned long long*>(&p);
    }
    if (blockIdx.x == 5) {
        for (int i = tid; i < NS * NC; i += CTHREADS) mu_s[i] = mu[i];
    }
    __syncthreads();

    if (blockIdx.x < 5) {
        // ---------------- C path ----------------
        const int col4 = blockIdx.x * CTHREADS + tid;      // float4 column, 0..1599
        const char* Dbase = reinterpret_cast<const char*>(D) + (size_t)col4 * 16;

        unsigned long long acc[R][2];
        #pragma unroll
        for (int r = 0; r < R; r++) { acc[r][0] = 0ull; acc[r][1] = 0ull; }

        #pragma unroll 5
        for (int j = 0; j < NS; j++) {
            const ulonglong2 d =
                *reinterpret_cast<const ulonglong2*>(Dbase + (size_t)j * (CD * 4));
            #pragma unroll
            for (int r2 = 0; r2 < R; r2 += 2) {
                // one LDS.128: pairs for rows r2 and r2+1
                const ulonglong2 aa =
                    *reinterpret_cast<const ulonglong2*>(&a2s[j * R + r2]);
                ffma2(acc[r2    ][0], d.x, aa.x);
                ffma2(acc[r2    ][1], d.y, aa.x);
                ffma2(acc[r2 + 1][0], d.x, aa.y);
                ffma2(acc[r2 + 1][1], d.y, aa.y);
            }
        }

        float* Cbase = C + (size_t)bt0 * CD + (size_t)col4 * 4;
        #pragma unroll
        for (int r = 0; r < R; r++) {
            ulonglong2 u;
            u.x = acc[r][0];
            u.y = acc[r][1];
            __stcs(reinterpret_cast<float4*>(Cbase + (size_t)r * CD),
                   *reinterpret_cast<float4*>(&u));
        }
    } else {
        // ---------------- m path (tiny) ----------------
        for (int o = tid; o < R * NC; o += CTHREADS) {
            const int r = o / NC, c = o % NC;
            float s = 0.0f;
            #pragma unroll
            for (int j = 0; j < NS; j++) {
                const float a = reinterpret_cast<const float2*>(&a2s[j * R + r])->x;
                s = fmaf(a, mu_s[j * NC + c], s);
            }
            __stcs(&m_out[(size_t)(bt0 + r) * NC + c], s);
        }
    }
}

extern "C" void kernel_launch(void* const* d_in, const int* in_sizes, int n_in,
                              void* d_out, int out_size)
{
    const float* alpha = (const float*)d_in[0];   // [64,400,25]
    const float* mu    = (const float*)d_in[1];   // [25,80]
    const float* D     = (const float*)d_in[2];   // [25,80,80]
    const float* asc   = (const float*)d_in[3];   // [25]

    float* out = (float*)d_out;
    float* m_out = out;                 // [64,400,80]
    float* c_out = out + M_ELEMS;       // [64,400,80,80]

    fused_kernel<<<dim3(6, BT / R), CTHREADS>>>(alpha, mu, D, asc, m_out, c_out);
}

// round 3
// speedup vs baseline: 1.0504x; 1.0007x over previous
#include <cuda_runtime.h>

#define NS 25
#define NC 80
#define CD (NC*NC)          // 6400
#define BATCH 64
#define TIME 400
#define BT (BATCH*TIME)     // 25600
#define M_ELEMS (BT*NC)     // 2,048,000

#define R 32                // bt rows per tile
#define NTILES (BT / R)     // 800
#define CTHREADS 320        // 320 thr * 4 floats = 1280 cols; 5 x-chunks cover 6400
#define YBLKS 29            // 5 * 29 = 145 blocks <= 148 SMs -> single wave

// Packed dual-FMA via f32x2 (PTX-only; doubles FFMA throughput)
__device__ __forceinline__ void ffma2(unsigned long long &acc,
                                      unsigned long long a,
                                      unsigned long long b) {
    asm("fma.rn.f32x2 %0, %1, %2, %0;" : "+l"(acc) : "l"(a), "l"(b));
}

__device__ __forceinline__ float softplus_f(float x) { return log1pf(expf(x)); }

// ---------------------------------------------------------------------------
// Persistent fused kernel. grid = (5, YBLKS). Block (x,y) owns the float4
// column range [x*320, x*320+320) and stride-loops tiles yt = y, y+YBLKS, ...
// D slice for a fixed x is 128 KB -> stays L1-resident across tiles.
// x==0 blocks additionally produce the m_t tile (tiny).
// ---------------------------------------------------------------------------
__global__ __launch_bounds__(CTHREADS, 1)
void fused_kernel(const float* __restrict__ alpha,
                  const float* __restrict__ mu,
                  const float* __restrict__ D,
                  const float* __restrict__ asc,
                  float* __restrict__ m_out,
                  float* __restrict__ C)
{
    __shared__ float scale_s[NS];
    __shared__ __align__(16) unsigned long long a2s[NS * R];  // [j][r] {a,a} pairs
    __shared__ float mu_s[NS * NC];                           // x==0 only

    const int tid = threadIdx.x;
    const bool do_m = (blockIdx.x == 0);

    if (tid < NS) scale_s[tid] = softplus_f(asc[tid]);
    if (do_m) {
        for (int i = tid; i < NS * NC; i += CTHREADS) mu_s[i] = mu[i];
    }

    const int col4 = blockIdx.x * CTHREADS + tid;          // float4 column
    const char* Dbase = reinterpret_cast<const char*>(D) + (size_t)col4 * 16;

    for (int yt = blockIdx.y; yt < NTILES; yt += YBLKS) {
        const int bt0 = yt * R;

        __syncthreads();   // protect a2s vs previous tile's readers (and scale_s, 1st iter)
        for (int i = tid; i < R * NS; i += CTHREADS) {
            const int r = i & (R - 1);
            const int j = i >> 5;
            const float v = alpha[(bt0 + r) * NS + j] * scale_s[j];
            float2 p = make_float2(v, v);
            a2s[j * R + r] = *reinterpret_cast<unsigned long long*>(&p);
        }
        __syncthreads();

        // ---------------- C tile ----------------
        unsigned long long acc[R][2];
        #pragma unroll
        for (int r = 0; r < R; r++) { acc[r][0] = 0ull; acc[r][1] = 0ull; }

        #pragma unroll 5
        for (int j = 0; j < NS; j++) {
            const ulonglong2 d =
                *reinterpret_cast<const ulonglong2*>(Dbase + (size_t)j * (CD * 4));
            #pragma unroll
            for (int r2 = 0; r2 < R; r2 += 2) {
                const ulonglong2 aa =
                    *reinterpret_cast<const ulonglong2*>(&a2s[j * R + r2]);
                ffma2(acc[r2    ][0], d.x, aa.x);
                ffma2(acc[r2    ][1], d.y, aa.x);
                ffma2(acc[r2 + 1][0], d.x, aa.y);
                ffma2(acc[r2 + 1][1], d.y, aa.y);
            }
        }

        float* Cbase = C + (size_t)bt0 * CD + (size_t)col4 * 4;
        #pragma unroll
        for (int r = 0; r < R; r++) {
            ulonglong2 u;
            u.x = acc[r][0];
            u.y = acc[r][1];
            __stcs(reinterpret_cast<float4*>(Cbase + (size_t)r * CD),
                   *reinterpret_cast<float4*>(&u));
        }

        // ---------------- m tile (x==0 blocks only) ----------------
        if (do_m) {
            for (int o = tid; o < R * NC; o += CTHREADS) {
                const int r = o / NC, c = o % NC;
                float s = 0.0f;
                #pragma unroll
                for (int j = 0; j < NS; j++) {
                    const float a = reinterpret_cast<const float2*>(&a2s[j * R + r])->x;
                    s = fmaf(a, mu_s[j * NC + c], s);
                }
                __stcs(&m_out[(size_t)(bt0 + r) * NC + c], s);
            }
        }
    }
}

extern "C" void kernel_launch(void* const* d_in, const int* in_sizes, int n_in,
                              void* d_out, int out_size)
{
    const float* alpha = (const float*)d_in[0];   // [64,400,25]
    const float* mu    = (const float*)d_in[1];   // [25,80]
    const float* D     = (const float*)d_in[2];   // [25,80,80]
    const float* asc   = (const float*)d_in[3];   // [25]

    float* out = (float*)d_out;
    float* m_out = out;                 // [64,400,80]
    float* c_out = out + M_ELEMS;       // [64,400,80,80]

    fused_kernel<<<dim3(5, YBLKS), CTHREADS>>>(alpha, mu, D, asc, m_out, c_out);
}